// round 5
// baseline (speedup 1.0000x reference)
#include <cuda_runtime.h>

typedef unsigned long long ull;

// ---------------- scratch (static device globals; no allocations) ----------------
__device__ float g_act1[800ull * 64 * 42 * 42];   // 361 MB
__device__ float g_act2[800ull * 64 * 21 * 21];   // 90 MB
__device__ float g_act3[800ull * 64 * 11 * 11];   // 25 MB
__device__ float g_emb [800ull * 2304];           // 7.4 MB
__device__ float g_w1t [3  * 9 * 64];
__device__ float g_w2t [64 * 9 * 64];
__device__ float g_w3t [64 * 9 * 64];
__device__ float g_w4t [64 * 9 * 64];
__device__ float g_protos[8 * 5 * 2304];
__device__ float g_pnorm[40];

// ---------------- packed f32x2 helpers (FFMA2: 2x fp32 FMA rate) ----------------
__device__ __forceinline__ void ffma2(ull &d, ull a, ull b) {
    asm("fma.rn.f32x2 %0, %1, %2, %0;" : "+l"(d) : "l"(a), "l"(b));
}
__device__ __forceinline__ ull pack2(float v) {
    ull r; asm("mov.b64 %0, {%1, %1};" : "=l"(r) : "f"(v)); return r;
}
__device__ __forceinline__ float2 unpack2(ull a) {
    float2 f; asm("mov.b64 {%0, %1}, %2;" : "=f"(f.x), "=f"(f.y) : "l"(a)); return f;
}

// ---------------- weight transpose: OIHW [oc][ic][kh][kw] -> [ic][k][oc] ----------------
__global__ void transpose_w(const float* __restrict__ W, float* __restrict__ out, int cin) {
    int i = blockIdx.x * blockDim.x + threadIdx.x;
    int total = 64 * cin * 9;
    if (i >= total) return;
    int oc  = i / (cin * 9);
    int rem = i % (cin * 9);
    int ic  = rem / 9;
    int k   = rem % 9;
    out[(ic * 9 + k) * 64 + oc] = W[i];
}

// ---------------- generic register-tiled direct conv (3x3, stride 2, relu) ----------------
// in : [nimg][CIN][IN_HW][IN_HW]
// wt : transposed weights [CIN][9][64]
// out: [nimg][64][OUT_HW][OUT_HW]
// PAD = pad_lo (XLA SAME). smem tile column c holds global col gc = c - PAD.
// smem tile row r (per chunk) holds global row gr = 2*r0 - PAD + r.
template<int CIN, int ICC, int IN_HW, int OUT_HW, int PAD, int RB, int TN, int CT>
__global__ void conv_k(const float* __restrict__ in, const float* __restrict__ wt,
                       const float* __restrict__ bias, float* __restrict__ out)
{
    constexpr int IN_ROWS = 2 * RB + 1;
    constexpr int W2 = IN_HW + 4;
    constexpr int SPT = RB * CT;

    __shared__ float s_in[ICC * IN_ROWS * W2];
    __shared__ __align__(16) float s_w[ICC * 9 * 64];

    const int img   = blockIdx.x;
    const int r0    = blockIdx.y * RB;
    const int tid   = threadIdx.x;
    const int ocg   = tid / SPT;           // 0..7
    const int spt   = tid % SPT;
    const int orow  = spt / CT;            // 0..RB-1
    const int ocol0 = (spt % CT) * TN;
    const int oc0   = ocg * 8;

    ull acc[4][TN];
#pragma unroll
    for (int p = 0; p < 4; p++)
#pragma unroll
        for (int t = 0; t < TN; t++) acc[p][t] = 0ull;

    const float* inb = in + (size_t)img * CIN * IN_HW * IN_HW;

    for (int ic0 = 0; ic0 < CIN; ic0 += ICC) {
        // stage input tile (zero-padded borders)
        for (int i = tid; i < ICC * IN_ROWS * W2; i += blockDim.x) {
            int c   = i % W2;
            int r   = (i / W2) % IN_ROWS;
            int icc = i / (W2 * IN_ROWS);
            int gr  = 2 * r0 - PAD + r;
            int gc  = c - PAD;
            float v = 0.f;
            if ((unsigned)gr < (unsigned)IN_HW && (unsigned)gc < (unsigned)IN_HW)
                v = inb[((size_t)(ic0 + icc) * IN_HW + gr) * IN_HW + gc];
            s_in[i] = v;
        }
        // stage weights chunk
        for (int i = tid; i < ICC * 9 * 64; i += blockDim.x)
            s_w[i] = wt[ic0 * 9 * 64 + i];
        __syncthreads();

        for (int icc = 0; icc < ICC; icc++) {
            const float* sin = s_in + ((size_t)icc * IN_ROWS + 2 * orow) * W2 + 2 * ocol0;
            const float* sw  = s_w + icc * 576 + oc0;
#pragma unroll
            for (int kh = 0; kh < 3; kh++) {
#pragma unroll
                for (int kw = 0; kw < 3; kw++) {
                    const float* srow = sin + kh * W2 + kw;
                    const ull* wv = (const ull*)(sw + (kh * 3 + kw) * 64);
                    ull w0 = wv[0], w1 = wv[1], w2 = wv[2], w3 = wv[3];
#pragma unroll
                    for (int t = 0; t < TN; t++) {
                        ull vv = pack2(srow[2 * t]);
                        ffma2(acc[0][t], vv, w0);
                        ffma2(acc[1][t], vv, w1);
                        ffma2(acc[2][t], vv, w2);
                        ffma2(acc[3][t], vv, w3);
                    }
                }
            }
        }
        __syncthreads();
    }

    // epilogue: bias + relu, write NCHW
    const int oh = r0 + orow;
    float* ob = out + (size_t)img * 64 * OUT_HW * OUT_HW;
#pragma unroll
    for (int p = 0; p < 4; p++) {
        float blo = bias[oc0 + 2 * p];
        float bhi = bias[oc0 + 2 * p + 1];
#pragma unroll
        for (int t = 0; t < TN; t++) {
            int ow = ocol0 + t;
            if ((OUT_HW % TN) != 0 && ow >= OUT_HW) continue;
            float2 v = unpack2(acc[p][t]);
            ob[((size_t)(oc0 + 2 * p)     * OUT_HW + oh) * OUT_HW + ow] = fmaxf(v.x + blo, 0.f);
            ob[((size_t)(oc0 + 2 * p + 1) * OUT_HW + oh) * OUT_HW + ow] = fmaxf(v.y + bhi, 0.f);
        }
    }
}

// ---------------- prototypes: segment-sum over classes / CAP(=5) ----------------
__global__ void proto_kernel(const float* __restrict__ emb_s, const int* __restrict__ y,
                             float* __restrict__ protos)
{
    int b = blockIdx.x, c = blockIdx.y;
    for (int d = threadIdx.x; d < 2304; d += blockDim.x) {
        float acc = 0.f;
#pragma unroll
        for (int s = 0; s < 25; s++) {
            if ((y[b * 25 + s] % 5) == c)
                acc += emb_s[(size_t)(b * 25 + s) * 2304 + d];
        }
        protos[(size_t)(b * 5 + c) * 2304 + d] = acc * 0.2f;
    }
}

__device__ __forceinline__ float block_reduce(float v, float* red) {
    red[threadIdx.x] = v;
    __syncthreads();
    for (int s = 128; s > 0; s >>= 1) {
        if (threadIdx.x < s) red[threadIdx.x] += red[threadIdx.x + s];
        __syncthreads();
    }
    float r = red[0];
    __syncthreads();
    return r;
}

__global__ void pnorm_kernel(const float* __restrict__ protos, float* __restrict__ pnorm) {
    __shared__ float red[256];
    const float* p = protos + (size_t)blockIdx.x * 2304;
    float s = 0.f;
    for (int d = threadIdx.x; d < 2304; d += 256) { float v = p[d]; s += v * v; }
    float tot = block_reduce(s, red);
    if (threadIdx.x == 0) pnorm[blockIdx.x] = fmaxf(sqrtf(tot), 1e-8f);
}

// ---------------- cosine-similarity logits ----------------
__global__ void logits_kernel(const float* __restrict__ emb, const float* __restrict__ protos,
                              const float* __restrict__ pnorm, float* __restrict__ out)
{
    __shared__ float red[256];
    int b = blockIdx.x / 75, t = blockIdx.x % 75;
    const float* q = emb + (size_t)(200 + b * 75 + t) * 2304;
    const float* P = protos + (size_t)b * 5 * 2304;

    float q2 = 0.f, dot[5] = {0.f, 0.f, 0.f, 0.f, 0.f};
    for (int d = threadIdx.x; d < 2304; d += 256) {
        float v = q[d];
        q2 += v * v;
#pragma unroll
        for (int c = 0; c < 5; c++) dot[c] += v * P[(size_t)c * 2304 + d];
    }
    float q2t = block_reduce(q2, red);
    float qn  = fmaxf(sqrtf(q2t), 1e-8f);
#pragma unroll
    for (int c = 0; c < 5; c++) {
        float dt = block_reduce(dot[c], red);
        if (threadIdx.x == 0)
            out[(size_t)(b * 75 + t) * 5 + c] = dt / (qn * pnorm[b * 5 + c]);
    }
}

// ---------------- launch ----------------
extern "C" void kernel_launch(void* const* d_in, const int* in_sizes, int n_in,
                              void* d_out, int out_size)
{
    const float* xs = (const float*)d_in[0];   // [8,25,3,84,84]
    const float* xt = (const float*)d_in[1];   // [8,75,3,84,84]
    const int*   y  = (const int*)  d_in[2];   // [8,25]
    const float* W1 = (const float*)d_in[3];
    const float* b1 = (const float*)d_in[4];
    const float* W2 = (const float*)d_in[5];
    const float* b2 = (const float*)d_in[6];
    const float* W3 = (const float*)d_in[7];
    const float* b3 = (const float*)d_in[8];
    const float* W4 = (const float*)d_in[9];
    const float* b4 = (const float*)d_in[10];
    float* out = (float*)d_out;

    float *act1, *act2, *act3, *emb, *w1t, *w2t, *w3t, *w4t, *protos, *pnorm;
    cudaGetSymbolAddress((void**)&act1,   g_act1);
    cudaGetSymbolAddress((void**)&act2,   g_act2);
    cudaGetSymbolAddress((void**)&act3,   g_act3);
    cudaGetSymbolAddress((void**)&emb,    g_emb);
    cudaGetSymbolAddress((void**)&w1t,    g_w1t);
    cudaGetSymbolAddress((void**)&w2t,    g_w2t);
    cudaGetSymbolAddress((void**)&w3t,    g_w3t);
    cudaGetSymbolAddress((void**)&w4t,    g_w4t);
    cudaGetSymbolAddress((void**)&protos, g_protos);
    cudaGetSymbolAddress((void**)&pnorm,  g_pnorm);

    transpose_w<<<(3  * 576 + 255) / 256, 256>>>(W1, w1t, 3);
    transpose_w<<<(64 * 576 + 255) / 256, 256>>>(W2, w2t, 64);
    transpose_w<<<(64 * 576 + 255) / 256, 256>>>(W3, w3t, 64);
    transpose_w<<<(64 * 576 + 255) / 256, 256>>>(W4, w4t, 64);

    // L1: 3->64, 84->42, pad_lo=0. RB=6,TN=7,CT=6 -> 288 threads, grid (nimg,7)
    conv_k<3, 3, 84, 42, 0, 6, 7, 6><<<dim3(200, 7), 288>>>(xs, w1t, b1, act1);
    conv_k<3, 3, 84, 42, 0, 6, 7, 6><<<dim3(600, 7), 288>>>(xt, w1t, b1,
                                                            act1 + 200ull * 64 * 42 * 42);
    // L2: 64->64, 42->21, pad_lo=0. RB=7,TN=7,CT=3 -> 168 threads, grid (800,3)
    conv_k<64, 8, 42, 21, 0, 7, 7, 3><<<dim3(800, 3), 168>>>(act1, w2t, b2, act2);
    // L3: 64->64, 21->11, pad_lo=1. RB=11,TN=6,CT=2 -> 176 threads, grid (800,1)
    conv_k<64, 8, 21, 11, 1, 11, 6, 2><<<dim3(800, 1), 176>>>(act2, w3t, b3, act3);
    // L4: 64->64, 11->6, pad_lo=1. RB=6,TN=3,CT=2 -> 96 threads, grid (800,1)
    conv_k<64, 8, 11, 6, 1, 6, 3, 2><<<dim3(800, 1), 96>>>(act3, w4t, b4, emb);

    proto_kernel<<<dim3(8, 5), 256>>>(emb, y, protos);
    pnorm_kernel<<<40, 256>>>(protos, pnorm);
    logits_kernel<<<600, 256>>>(emb, protos, pnorm, out);
}